// round 17
// baseline (speedup 1.0000x reference)
#include <cuda_runtime.h>
#include <cstdint>

#define N_NODES 2048
#define IN_DIM 32
#define LATENT 64

// Scratch (__device__ globals: allocation-free rule)
__device__ float g_ziT[LATENT * N_NODES];   // [l][n]: zi transposed
__device__ float g_zbT[LATENT * N_NODES];   // [l][n]: zjb transposed
__device__ float g_ws[LATENT];              // 0.495 * w
__device__ float g_aw2[N_NODES];            // 0.505 * dot(w, zi[i])
__device__ float g_cw2[N_NODES];            // 0.505 * dot(w, zjb[j]) + b_e2

// ---------------------------------------------------------------------------
// Kernel 1: per-node precompute, 8 nodes/block -> 256 blocks.
// ---------------------------------------------------------------------------
__global__ __launch_bounds__(256) void node_precompute_kernel(
    const float* __restrict__ x,
    const float* __restrict__ W_ne, const float* __restrict__ b_ne,
    const float* __restrict__ W_e1a, const float* __restrict__ W_e1b,
    const float* __restrict__ b_e1,
    const float* __restrict__ w_e2, const float* __restrict__ b_e2)
{
    __shared__ float sWne[IN_DIM * LATENT];
    __shared__ float sWa[LATENT * LATENT];
    __shared__ float sWb[LATENT * LATENT];
    __shared__ float sx[8][IN_DIM];
    __shared__ float sz[8][LATENT];
    __shared__ float szi[8][LATENT];
    __shared__ float szjb[8][LATENT];

    const int tid = threadIdx.x;
    const int nb = blockIdx.x * 8;

    for (int i = tid; i < IN_DIM * LATENT / 4; i += 256)
        ((float4*)sWne)[i] = ((const float4*)W_ne)[i];
    for (int i = tid; i < LATENT * LATENT / 4; i += 256) {
        ((float4*)sWa)[i] = ((const float4*)W_e1a)[i];
        ((float4*)sWb)[i] = ((const float4*)W_e1b)[i];
    }
    if (tid < 64)
        ((float4*)sx)[tid] = ((const float4*)&x[nb * IN_DIM])[tid];
    __syncthreads();

    // phase 1: z = lrelu(x @ W_ne + b_ne), 512 outputs, 2/thread
#pragma unroll
    for (int r = 0; r < 2; r++) {
        int idx = tid + 256 * r;
        int n = idx >> 6, l = idx & 63;
        float acc = b_ne[l];
#pragma unroll
        for (int k = 0; k < IN_DIM; k++)
            acc = fmaf(sx[n][k], sWne[k * LATENT + l], acc);
        sz[n][l] = fmaxf(acc, 0.01f * acc);
    }
    __syncthreads();

    // phase 2: 2 latents/thread; warp-uniform node (z broadcast)
    {
        const int n = tid >> 5;           // 0..7
        const int l0 = (tid & 31) * 2;    // 0,2,..,62
        float zi0 = 0.f, zi1 = 0.f;
        float zj0, zj1;
        {
            const float2 b2 = *(const float2*)&b_e1[l0];
            zj0 = b2.x; zj1 = b2.y;
        }
#pragma unroll
        for (int k4 = 0; k4 < LATENT / 4; k4++) {
            const float4 z4 = *(const float4*)&sz[n][k4 * 4];  // broadcast
            const float zk[4] = {z4.x, z4.y, z4.z, z4.w};
#pragma unroll
            for (int m = 0; m < 4; m++) {
                const int k = k4 * 4 + m;
                const float2 wa = *(const float2*)&sWa[k * LATENT + l0];
                const float2 wb = *(const float2*)&sWb[k * LATENT + l0];
                zi0 = fmaf(zk[m], wa.x, zi0);
                zi1 = fmaf(zk[m], wa.y, zi1);
                zj0 = fmaf(zk[m], wb.x, zj0);
                zj1 = fmaf(zk[m], wb.y, zj1);
            }
        }
        *(float2*)&szi[n][l0]  = make_float2(zi0, zi1);
        *(float2*)&szjb[n][l0] = make_float2(zj0, zj1);
        // transposed scatters (4B stores, tiny volume)
        g_ziT[(size_t)l0 * N_NODES + nb + n] = zi0;
        g_ziT[(size_t)(l0 + 1) * N_NODES + nb + n] = zi1;
        g_zbT[(size_t)l0 * N_NODES + nb + n] = zj0;
        g_zbT[(size_t)(l0 + 1) * N_NODES + nb + n] = zj1;
    }
    __syncthreads();

    // reductions: warp w handles node w
    const int wid = tid >> 5, lane = tid & 31;
    const float w1 = w_e2[lane], w2 = w_e2[lane + 32];
    float s1 = w1 * szi[wid][lane]  + w2 * szi[wid][lane + 32];
    float s2 = w1 * szjb[wid][lane] + w2 * szjb[wid][lane + 32];
#pragma unroll
    for (int off = 16; off > 0; off >>= 1) {
        s1 += __shfl_down_sync(0xffffffffu, s1, off);
        s2 += __shfl_down_sync(0xffffffffu, s2, off);
    }
    if (lane == 0) {
        g_aw2[nb + wid] = 0.505f * s1;
        g_cw2[nb + wid] = 0.505f * s2 + b_e2[0];
    }
    if (blockIdx.x == 0 && tid < LATENT)
        g_ws[tid] = 0.495f * w_e2[tid];
}

// ---------------------------------------------------------------------------
// Kernel 2: 64x64 tile, 256 threads, 4i x 4j outputs/thread, BOTH operand
// tables transposed [lat][node] -> per latent: 1 LDS32 w + 1 LDS128 a +
// 1 LDS128 b, abs folded into FFMA |operand|. Low live-set -> 5 blocks/SM.
// logit(i,j) = aw2[i] + cw2[j] + sum_l ws[l] * |zi[i,l] + zjb[j,l]|
// out = (sigmoid(logit) + 1e-8) * exp(gumbel)
// ---------------------------------------------------------------------------
__global__ __launch_bounds__(256, 5) void edge_prob_kernel(
    const float* __restrict__ gumbel, float* __restrict__ out)
{
    extern __shared__ char smem_raw[];
    float* s_ziT  = (float*)smem_raw;                    // [64][64]   16384B
    float* s_zjbT = (float*)(smem_raw + 16384);          // [64][64]   16384B
    float* s_ws   = (float*)(smem_raw + 32768);          // [64]         256B
    float* s_aw   = (float*)(smem_raw + 33024);          // [64]         256B
    float* s_cw   = (float*)(smem_raw + 33280);          // [64]         256B

    const int tid = threadIdx.x;
    const int ibase = blockIdx.y * 64;
    const int jbase = blockIdx.x * 64;

    // load phase (coalesced float4 from pre-transposed globals)
#pragma unroll
    for (int t = tid; t < 1024; t += 256) {
        int r = t >> 4, c4 = (t & 15) * 4;   // r: latent, c4: node col
        *(float4*)&s_ziT[r * 64 + c4] =
            *(const float4*)&g_ziT[(size_t)r * N_NODES + ibase + c4];
        *(float4*)&s_zjbT[r * 64 + c4] =
            *(const float4*)&g_zbT[(size_t)r * N_NODES + jbase + c4];
    }
    if (tid < 64) {
        s_ws[tid] = g_ws[tid];
        s_aw[tid] = g_aw2[ibase + tid];
        s_cw[tid] = g_cw2[jbase + tid];
    }
    __syncthreads();

    const int tx = tid & 15;   // j sub-tile
    const int ty = tid >> 4;   // i sub-tile

    float acc[4][4] = {};

#pragma unroll 4
    for (int l = 0; l < LATENT; l++) {
        const float w = s_ws[l];                                 // broadcast
        const float4 a4 = *(const float4*)&s_ziT[l * 64 + ty * 4];  // 4 i-vals
        const float4 b4 = *(const float4*)&s_zjbT[l * 64 + tx * 4]; // 4 j-vals
        const float a[4] = {a4.x, a4.y, a4.z, a4.w};
        const float b[4] = {b4.x, b4.y, b4.z, b4.w};
#pragma unroll
        for (int ii = 0; ii < 4; ii++) {
#pragma unroll
            for (int jj = 0; jj < 4; jj++) {
                // plain fabsf -> folded as |operand| into the FFMA
                acc[ii][jj] = fmaf(w, fabsf(a[ii] + b[jj]), acc[ii][jj]);
            }
        }
    }

    // epilogue
#pragma unroll
    for (int ii = 0; ii < 4; ii++) {
        const int i = ibase + ty * 4 + ii;
        const int j0 = jbase + tx * 4;
        const float base_i = s_aw[ty * 4 + ii];
        const size_t off = (size_t)i * N_NODES + j0;
        const float4 gv = *(const float4*)&gumbel[off];
        const float g4[4] = {gv.x, gv.y, gv.z, gv.w};
        float4 o;
        float* op = &o.x;
#pragma unroll
        for (int jj = 0; jj < 4; jj++) {
            float logit = acc[ii][jj] + base_i + s_cw[tx * 4 + jj];
            float e = __expf(-logit);
            float p = __fdividef(1.0f, 1.0f + e);
            op[jj] = (p + 1e-8f) * __expf(g4[jj]);
        }
        *(float4*)&out[off] = o;
    }
}

// ---------------------------------------------------------------------------
// Inputs (metadata order):
// 0:x [N,32] 1:in_adj [N,N](unused) 2:gumbel [N,N] 3:W_ne [32,64] 4:b_ne [64]
// 5:W_e1a [64,64] 6:W_e1b [64,64] 7:b_e1 [64] 8:w_e2 [64] 9:b_e2 []
// out: [N,N] float32
// ---------------------------------------------------------------------------
extern "C" void kernel_launch(void* const* d_in, const int* in_sizes, int n_in,
                              void* d_out, int out_size)
{
    const float* x      = (const float*)d_in[0];
    const float* gumbel = (const float*)d_in[2];
    const float* W_ne   = (const float*)d_in[3];
    const float* b_ne   = (const float*)d_in[4];
    const float* W_e1a  = (const float*)d_in[5];
    const float* W_e1b  = (const float*)d_in[6];
    const float* b_e1   = (const float*)d_in[7];
    const float* w_e2   = (const float*)d_in[8];
    const float* b_e2   = (const float*)d_in[9];
    float* out = (float*)d_out;

    node_precompute_kernel<<<N_NODES / 8, 256>>>(x, W_ne, b_ne, W_e1a, W_e1b,
                                                 b_e1, w_e2, b_e2);

    static bool attr_set = false;
    if (!attr_set) {
        cudaFuncSetAttribute(edge_prob_kernel,
                             cudaFuncAttributeMaxDynamicSharedMemorySize, 33536);
        attr_set = true;
    }
    dim3 grid(N_NODES / 64, N_NODES / 64);
    edge_prob_kernel<<<grid, 256, 33536>>>(gumbel, out);
}